// round 4
// baseline (speedup 1.0000x reference)
#include <cuda_runtime.h>
#include <cstdint>

#define TT 32
#define NCTA 128

// ---------------- scratch (device globals: allocation-free) ----------------
static __device__ float g_A   [(size_t)128 * 1024 * 512];  // [b*32+t][n][512] 256MB
static __device__ float g_out0[(size_t)4 * 32 * 132 * 1024];
static __device__ float g_Hh  [(size_t)4 * 1024 * 512];
static __device__ float g_cb  [2][(size_t)4 * 1024 * 128];
static __device__ int   g_idx [(size_t)4 * 32 * 1024 * 16];
static __device__ float g_wEA0[512 * 4];
static __device__ float g_wEA1[512 * 132];
static __device__ unsigned g_bar;

// ---------------- helpers ----------------
__device__ __forceinline__ void fma2(unsigned long long& acc, unsigned long long a,
                                     unsigned long long b) {
    asm("fma.rn.f32x2 %0, %1, %2, %3;" : "=l"(acc) : "l"(a), "l"(b), "l"(acc));
}
__device__ __forceinline__ unsigned long long dup2(float w) {
    unsigned long long r;
    asm("mov.b64 %0, {%1, %1};" : "=l"(r) : "f"(w));
    return r;
}
__device__ __forceinline__ float tanha(float x) {
    float y;
    asm("tanh.approx.f32 %0, %1;" : "=f"(y) : "f"(x));
    return y;
}
__device__ __forceinline__ float sigm(float x) {
    return fmaf(0.5f, tanha(0.5f * x), 0.5f);
}

// ---------------- KNN: stable top-16 of d2 = q2 + r2 - 2 q.r ----------------
__global__ __launch_bounds__(256) void knn_kernel(const float* __restrict__ x,
                                                  float* __restrict__ outG,
                                                  int* __restrict__ idxOut) {
    __shared__ float rx[1024], ry[1024], rz[1024], rs[1024];
    int b = blockIdx.z, t = blockIdx.y;
    int n = blockIdx.x * 256 + threadIdx.x;
    int prev = t ? t - 1 : 0;
    const float* rb = x + (size_t)(b * TT + prev) * 4 * 1024;
    for (int i = threadIdx.x; i < 1024; i += 256) {
        float a = rb[i], c = rb[1024 + i], d = rb[2048 + i];
        rx[i] = a; ry[i] = c; rz[i] = d;
        rs[i] = __fadd_rn(__fadd_rn(__fmul_rn(a, a), __fmul_rn(c, c)), __fmul_rn(d, d));
    }
    __syncthreads();
    const float* qb = x + (size_t)(b * TT + t) * 4 * 1024;
    float qx = qb[n], qy = qb[1024 + n], qz = qb[2048 + n];
    float q2 = __fadd_rn(__fadd_rn(__fmul_rn(qx, qx), __fmul_rn(qy, qy)), __fmul_rn(qz, qz));
    float bd[16]; int bi[16];
#pragma unroll
    for (int i = 0; i < 16; i++) { bd[i] = 3.4e38f; bi[i] = 0; }
    for (int m = 0; m < 1024; m++) {
        float qr = fmaf(qz, rz[m], fmaf(qy, ry[m], __fmul_rn(qx, rx[m])));
        float d2 = (q2 + rs[m]) - 2.0f * qr;
        if (d2 < bd[15]) {
            int pos = 0;
#pragma unroll
            for (int i = 0; i < 16; i++) pos += (bd[i] <= d2) ? 1 : 0;  // stable ties
#pragma unroll
            for (int i = 15; i > 0; i--)
                if (i > pos) { bd[i] = bd[i - 1]; bi[i] = bi[i - 1]; }
#pragma unroll
            for (int i = 0; i < 16; i++)
                if (i == pos) { bd[i] = d2; bi[i] = m; }
        }
    }
    size_t o = (size_t)((b * TT + t) * 1024 + n) * 16;
#pragma unroll
    for (int k = 0; k < 16; k++) { idxOut[o + k] = bi[k]; outG[o + k] = (float)bi[k]; }
}

// ------- weight prep: fold "-x_t[:4]" (pos adjust) into the A-path weights -------
__global__ void setup_kernel(const float* __restrict__ w0, const float* __restrict__ w1,
                             float* __restrict__ wEA0, float* __restrict__ wEA1) {
    int i = blockIdx.x * 256 + threadIdx.x;
    if (i < 512 * 4) {
        int o = i >> 2, j = i & 3;
        wEA0[i] = w0[o * 136 + j] - w0[o * 136 + 4 + j];
    }
    if (i < 512 * 132) {
        int o = i / 132, c = i % 132;
        float v = w1[o * 264 + c];
        if (c < 4) v -= w1[o * 264 + 132 + c];
        wEA1[i] = v;
    }
}

// ------- copy position channels into both layer-output buffers (ch 0..3 of 132) ---
__global__ void copypos_kernel(const float* __restrict__ x, float* __restrict__ out,
                               float* __restrict__ out0) {
    int i = blockIdx.x * 256 + threadIdx.x;  // 524288 = 4*32*4*1024
    int n = i & 1023;
    int c = (i >> 10) & 3;
    int bt = i >> 12;
    float v = x[i];
    size_t dst = ((size_t)bt * 132 + c) * 1024 + n;
    out[dst] = v;
    out0[dst] = v;
}

// ---- hoisted A GEMM: Out[z][m][o] = bias[o] + sum_j W[o][j]*In_z[j][m] ----
__global__ __launch_bounds__(256) void gemm_kernel(
    const float* __restrict__ In0, long inZ,
    const float* __restrict__ W, int ldw, int Kdim,
    const float* __restrict__ bias,
    float* __restrict__ Out0, long outZ) {
    __shared__ float sIn[16][128];
    __shared__ float sW[16][65];
    int z = blockIdx.z;
    const float* In = In0 + (size_t)z * inZ;
    float* Out = Out0 + (size_t)z * outZ;
    int mTile = blockIdx.x * 128;
    int oTile = blockIdx.y * 64;
    int tid = threadIdx.x;
    int tx = tid & 15, ty = tid >> 4;
    unsigned long long acc[4][4];
#pragma unroll
    for (int a = 0; a < 4; a++)
#pragma unroll
        for (int c = 0; c < 4; c++) acc[a][c] = 0ULL;
    int nkt = (Kdim + 15) >> 4;
    for (int kt = 0; kt < nkt; kt++) {
        int k0 = kt << 4;
        for (int i = tid; i < 2048; i += 256) {
            int j = i >> 7, mm = i & 127;
            sIn[j][mm] = (k0 + j < Kdim) ? In[(size_t)(k0 + j) * 1024 + mTile + mm] : 0.f;
        }
        for (int i = tid; i < 1024; i += 256) {
            int j = i & 15, o = i >> 4;
            sW[j][o] = (k0 + j < Kdim) ? W[(size_t)(oTile + o) * ldw + k0 + j] : 0.f;
        }
        __syncthreads();
#pragma unroll
        for (int j = 0; j < 16; j++) {
            unsigned long long iv[4], wv[4];
#pragma unroll
            for (int s = 0; s < 4; s++)
                iv[s] = *reinterpret_cast<const unsigned long long*>(&sIn[j][ty * 2 + 32 * s]);
#pragma unroll
            for (int s = 0; s < 4; s++) wv[s] = dup2(sW[j][tx + 16 * s]);
#pragma unroll
            for (int mi = 0; mi < 4; mi++)
#pragma unroll
                for (int oi = 0; oi < 4; oi++) fma2(acc[mi][oi], iv[mi], wv[oi]);
        }
        __syncthreads();
    }
#pragma unroll
    for (int mi = 0; mi < 4; mi++) {
        int m = mTile + ty * 2 + 32 * mi;
#pragma unroll
        for (int oi = 0; oi < 4; oi++) {
            int o = oTile + tx + 16 * oi;
            float lo, hi;
            asm("mov.b64 {%0, %1}, %2;" : "=f"(lo), "=f"(hi) : "l"(acc[mi][oi]));
            float add = bias ? bias[o] : 0.f;
            size_t p0 = (size_t)m * 512 + o;
            Out[p0] = lo + add;
            Out[p0 + 512] = hi + add;
        }
    }
}

// ---------------- barrier reset ----------------
__global__ void reset_kernel() { g_bar = 0; }

__device__ __forceinline__ void grid_barrier(unsigned gen) {
    __syncthreads();
    if (threadIdx.x == 0) {
        __threadfence();
        atomicAdd(&g_bar, 1u);
        unsigned target = gen * NCTA;
        while (*((volatile unsigned*)&g_bar) < target) __nanosleep(64);
    }
    __syncthreads();
    __threadfence();  // membar.gl (gpu scope) -> orders + L1D invalidate on sm_103a
}

// ---------------- persistent per-layer recurrent kernel ----------------
// Phase A (GEMM): Hh[b][m][o] = sum_k W[o][k] * outbuf[b][t-1][k][m], K=132 (t=0: K=4)
// Phase B: gather gates, LSTM nonlin, max over k, write h->outbuf[t] ch4..131, c->cb
__global__ __launch_bounds__(256) void persist_kernel(
    float* __restrict__ outbuf, const float* __restrict__ W, int ldw,
    const float* __restrict__ A, const int* __restrict__ idxAll,
    float* __restrict__ cb) {
    __shared__ float sIn[16][128];
    __shared__ float sW[16][65];
    __shared__ float sh[128][33];
    const int tid = threadIdx.x;
    const int cta = blockIdx.x;
    const int tx = tid & 15, ty = tid >> 4;
    const int oT = cta & 7;   // 8 o-tiles of 64
    const int pq = cta >> 3;  // 0..15 -> 2 (b,mT) tiles each
    const int warp = tid >> 5, lane = tid & 31;
    const int bB = cta >> 5;           // batch for stepB
    const int n0 = (cta & 31) * 32;    // n base for stepB
    unsigned bcount = 0;

    for (int t = 0; t < TT; t++) {
        // ================= GEMM phase =================
        const int Kdim = (t == 0) ? 4 : 132;
        const int tprev = (t == 0) ? 0 : t - 1;
        const int nkt = (Kdim + 15) >> 4;
        for (int tile = 2 * pq; tile < 2 * pq + 2; tile++) {
            const int b = tile >> 3;
            const int mTile = (tile & 7) * 128;
            const float* In = outbuf + (size_t)(b * TT + tprev) * 132 * 1024;
            float* Out = g_Hh + (size_t)b * 1024 * 512;
            unsigned long long acc[4][4];
#pragma unroll
            for (int a = 0; a < 4; a++)
#pragma unroll
                for (int c = 0; c < 4; c++) acc[a][c] = 0ULL;
            for (int kt = 0; kt < nkt; kt++) {
                int k0 = kt << 4;
                for (int i = tid; i < 2048; i += 256) {
                    int j = i >> 7, mm = i & 127;
                    sIn[j][mm] = (k0 + j < Kdim)
                        ? __ldcg(&In[(size_t)(k0 + j) * 1024 + mTile + mm]) : 0.f;
                }
                for (int i = tid; i < 1024; i += 256) {
                    int j = i & 15, o = i >> 4;
                    sW[j][o] = (k0 + j < Kdim)
                        ? W[(size_t)(oT * 64 + o) * ldw + k0 + j] : 0.f;
                }
                __syncthreads();
#pragma unroll
                for (int j = 0; j < 16; j++) {
                    unsigned long long iv[4], wv[4];
#pragma unroll
                    for (int s = 0; s < 4; s++)
                        iv[s] = *reinterpret_cast<const unsigned long long*>(
                            &sIn[j][ty * 2 + 32 * s]);
#pragma unroll
                    for (int s = 0; s < 4; s++) wv[s] = dup2(sW[j][tx + 16 * s]);
#pragma unroll
                    for (int mi = 0; mi < 4; mi++)
#pragma unroll
                        for (int oi = 0; oi < 4; oi++) fma2(acc[mi][oi], iv[mi], wv[oi]);
                }
                __syncthreads();
            }
#pragma unroll
            for (int mi = 0; mi < 4; mi++) {
                int m = mTile + ty * 2 + 32 * mi;
#pragma unroll
                for (int oi = 0; oi < 4; oi++) {
                    int o = oT * 64 + tx + 16 * oi;
                    float lo, hi;
                    asm("mov.b64 {%0, %1}, %2;" : "=f"(lo), "=f"(hi) : "l"(acc[mi][oi]));
                    size_t p0 = (size_t)m * 512 + o;
                    Out[p0] = lo;
                    Out[p0 + 512] = hi;
                }
            }
        }
        grid_barrier(++bcount);

        // ================= stepB phase =================
        {
            const float* cpB = cb + (size_t)((t & 1) * 4 + bB) * 1024 * 128;
            float* coB = cb + (size_t)(((t + 1) & 1) * 4 + bB) * 1024 * 128;
            const float* HhB = g_Hh + (size_t)bB * 1024 * 512;
            for (int i = 0; i < 4; i++) {
                int n = n0 + warp * 4 + i;
                const float* Arow = A + ((size_t)(bB * TT + t) * 1024 + n) * 512;
                const int* idxr = idxAll + ((size_t)(bB * TT + t) * 1024 + n) * 16;
                float Ai[4], Af[4], Ao[4], Ag[4], hm[4], cm[4];
#pragma unroll
                for (int j = 0; j < 4; j++) {
                    int d = j * 32 + lane;
                    Ai[j] = Arow[d];
                    Af[j] = Arow[128 + d];
                    Ao[j] = Arow[256 + d];
                    Ag[j] = Arow[384 + d];
                    hm[j] = -3.4e38f;
                    cm[j] = -3.4e38f;
                }
#pragma unroll 2
                for (int k = 0; k < 16; k++) {
                    int m = idxr[k];
                    const float* Hr = HhB + (size_t)m * 512;
                    const float* cr = cpB + (size_t)m * 128;
#pragma unroll
                    for (int j = 0; j < 4; j++) {
                        int d = j * 32 + lane;
                        float gi = Ai[j] + __ldcg(Hr + d);
                        float gf = Af[j] + __ldcg(Hr + 128 + d);
                        float go = Ao[j] + __ldcg(Hr + 256 + d);
                        float gg = Ag[j] + __ldcg(Hr + 384 + d);
                        float cgv = (t == 0) ? 0.f : __ldcg(cr + d);
                        float cn = sigm(gf) * cgv + sigm(gi) * tanha(gg);
                        float hn = sigm(go) * tanha(cn);
                        cm[j] = fmaxf(cm[j], cn);
                        hm[j] = fmaxf(hm[j], hn);
                    }
                }
                float* co = coB + (size_t)n * 128;
#pragma unroll
                for (int j = 0; j < 4; j++) co[j * 32 + lane] = cm[j];
#pragma unroll
                for (int j = 0; j < 4; j++) sh[j * 32 + lane][warp * 4 + i] = hm[j];
            }
            __syncthreads();
            float* ho = outbuf + ((size_t)(bB * TT + t) * 132 + 4) * 1024 + n0;
            for (int i2 = tid; i2 < 4096; i2 += 256) {
                int d = i2 >> 5, nn = i2 & 31;
                ho[(size_t)d * 1024 + nn] = sh[d][nn];
            }
        }
        grid_barrier(++bcount);
    }
}

// ------- final: h copy from out1[t=31], c transpose [b][n][d] -> [b][d][n] --------
__global__ void final_kernel(float* __restrict__ out, const float* __restrict__ cfin) {
    int i = blockIdx.x * 256 + threadIdx.x;  // 524288 = 4*128*1024
    int b = i >> 17;
    int r = i & 131071;
    int d = r >> 10;
    int n = r & 1023;
    out[17301504 + i] = out[((size_t)((b * 32 + 31) * 132) + 4 + d) * 1024 + n];
    out[17825792 + i] = cfin[(size_t)(b * 1024 + n) * 128 + d];
}

// ---------------- launch ----------------
extern "C" void kernel_launch(void* const* d_in, const int* in_sizes, int n_in,
                              void* d_out, int out_size) {
    const float* x = (const float*)d_in[0];
    const float* w0 = (const float*)d_in[1];
    const float* b0 = (const float*)d_in[2];
    const float* w1 = (const float*)d_in[3];
    const float* b1 = (const float*)d_in[4];
    float* out = (float*)d_out;

    float *A, *out0, *cb, *wEA0, *wEA1;
    int* idxp;
    cudaGetSymbolAddress((void**)&A, g_A);
    cudaGetSymbolAddress((void**)&out0, g_out0);
    cudaGetSymbolAddress((void**)&cb, g_cb);
    cudaGetSymbolAddress((void**)&wEA0, g_wEA0);
    cudaGetSymbolAddress((void**)&wEA1, g_wEA1);
    cudaGetSymbolAddress((void**)&idxp, g_idx);

    const long Z = 1024L * 512;

    knn_kernel<<<dim3(4, 32, 4), 256>>>(x, out + 18350080, idxp);
    setup_kernel<<<264, 256>>>(w0, w1, wEA0, wEA1);
    copypos_kernel<<<2048, 256>>>(x, out, out0);

    // layer 0: hoisted A (K=4 folded), then persistent 32-step loop
    gemm_kernel<<<dim3(8, 8, 128), 256>>>(x, 4096L, wEA0, 4, 4, b0, A, Z);
    reset_kernel<<<1, 1>>>();
    persist_kernel<<<NCTA, 256>>>(out0, w0 + 4, 136, A, idxp, cb);

    // layer 1: hoisted A (K=132 folded over out0), then persistent loop
    gemm_kernel<<<dim3(8, 8, 128), 256>>>(out0, 132L * 1024, wEA1, 132, 132, b1, A, Z);
    reset_kernel<<<1, 1>>>();
    persist_kernel<<<NCTA, 256>>>(out, w1 + 132, 264, A, idxp, cb);

    final_kernel<<<2048, 256>>>(out, cb);
}

// round 6
// speedup vs baseline: 1.4549x; 1.4549x over previous
#include <cuda_runtime.h>
#include <cstdint>

#define TT 32

// ---------------- scratch (device globals: allocation-free) ----------------
static __device__ float g_A   [(size_t)128 * 1024 * 512];  // layer1 A: [b*32+t][n][512]
static __device__ float g_out0[(size_t)4 * 32 * 132 * 1024];
static __device__ float g_Hh  [(size_t)4 * 1024 * 512];
static __device__ float g_cb  [2][(size_t)4 * 1024 * 128];
static __device__ int   g_idx [(size_t)4 * 32 * 1024 * 16];
static __device__ float g_wEA0[512 * 4];
static __device__ float g_wEA1[512 * 132];

// ---------------- helpers ----------------
__device__ __forceinline__ void fma2(unsigned long long& acc, unsigned long long a,
                                     unsigned long long b) {
    asm("fma.rn.f32x2 %0, %1, %2, %3;" : "=l"(acc) : "l"(a), "l"(b), "l"(acc));
}
__device__ __forceinline__ unsigned long long dup2(float w) {
    unsigned long long r;
    asm("mov.b64 %0, {%1, %1};" : "=l"(r) : "f"(w));
    return r;
}
__device__ __forceinline__ float tanha(float x) {
    float y;
    asm("tanh.approx.f32 %0, %1;" : "=f"(y) : "f"(x));
    return y;
}
__device__ __forceinline__ float sigm(float x) {
    return fmaf(0.5f, tanha(0.5f * x), 0.5f);
}

// ---------------- KNN: stable top-16 of d2 = q2 + r2 - 2 q.r ----------------
__global__ __launch_bounds__(256) void knn_kernel(const float* __restrict__ x,
                                                  float* __restrict__ outG,
                                                  int* __restrict__ idxOut) {
    __shared__ float rx[1024], ry[1024], rz[1024], rs[1024];
    int b = blockIdx.z, t = blockIdx.y;
    int n = blockIdx.x * 256 + threadIdx.x;
    int prev = t ? t - 1 : 0;
    const float* rb = x + (size_t)(b * TT + prev) * 4 * 1024;
    for (int i = threadIdx.x; i < 1024; i += 256) {
        float a = rb[i], c = rb[1024 + i], d = rb[2048 + i];
        rx[i] = a; ry[i] = c; rz[i] = d;
        rs[i] = __fadd_rn(__fadd_rn(__fmul_rn(a, a), __fmul_rn(c, c)), __fmul_rn(d, d));
    }
    __syncthreads();
    const float* qb = x + (size_t)(b * TT + t) * 4 * 1024;
    float qx = qb[n], qy = qb[1024 + n], qz = qb[2048 + n];
    float q2 = __fadd_rn(__fadd_rn(__fmul_rn(qx, qx), __fmul_rn(qy, qy)), __fmul_rn(qz, qz));
    float bd[16]; int bi[16];
#pragma unroll
    for (int i = 0; i < 16; i++) { bd[i] = 3.4e38f; bi[i] = 0; }
    for (int m = 0; m < 1024; m++) {
        float qr = fmaf(qz, rz[m], fmaf(qy, ry[m], __fmul_rn(qx, rx[m])));
        float d2 = (q2 + rs[m]) - 2.0f * qr;
        if (d2 < bd[15]) {
            int pos = 0;
#pragma unroll
            for (int i = 0; i < 16; i++) pos += (bd[i] <= d2) ? 1 : 0;  // stable ties
#pragma unroll
            for (int i = 15; i > 0; i--)
                if (i > pos) { bd[i] = bd[i - 1]; bi[i] = bi[i - 1]; }
#pragma unroll
            for (int i = 0; i < 16; i++)
                if (i == pos) { bd[i] = d2; bi[i] = m; }
        }
    }
    size_t o = (size_t)((b * TT + t) * 1024 + n) * 16;
#pragma unroll
    for (int k = 0; k < 16; k++) { idxOut[o + k] = bi[k]; outG[o + k] = (float)bi[k]; }
}

// ------- weight prep: fold "-x_t[:4]" (pos adjust) into the A-path weights -------
__global__ void setup_kernel(const float* __restrict__ w0, const float* __restrict__ w1,
                             float* __restrict__ wEA0, float* __restrict__ wEA1) {
    int i = blockIdx.x * 256 + threadIdx.x;
    if (i < 512 * 4) {
        int o = i >> 2, j = i & 3;
        wEA0[i] = w0[o * 136 + j] - w0[o * 136 + 4 + j];
    }
    if (i < 512 * 132) {
        int o = i / 132, c = i % 132;
        float v = w1[o * 264 + c];
        if (c < 4) v -= w1[o * 264 + 132 + c];
        wEA1[i] = v;
    }
}

// ------- copy position channels into both layer-output buffers (ch 0..3 of 132) ---
__global__ void copypos_kernel(const float* __restrict__ x, float* __restrict__ out,
                               float* __restrict__ out0) {
    int i = blockIdx.x * 256 + threadIdx.x;  // 524288 = 4*32*4*1024
    int n = i & 1023;
    int c = (i >> 10) & 3;
    int bt = i >> 12;
    float v = x[i];
    size_t dst = ((size_t)bt * 132 + c) * 1024 + n;
    out[dst] = v;
    out0[dst] = v;
}

// ---- GEMM 128x128 tile: Out[z][m][o(512)] = bias[o] + sum_j W[o][j]*In_z[j][m] ----
__global__ __launch_bounds__(256) void gemm_kernel(
    const float* __restrict__ In0, long inZ,
    const float* __restrict__ W, int ldw, int Kdim,
    const float* __restrict__ bias,
    float* __restrict__ Out0, long outZ) {
    __shared__ float sIn[16][128];
    __shared__ float sW[16][129];
    int z = blockIdx.z;
    const float* In = In0 + (size_t)z * inZ;
    float* Out = Out0 + (size_t)z * outZ;
    int mTile = blockIdx.x * 128;
    int oTile = blockIdx.y * 128;
    int tid = threadIdx.x;
    int tx = tid & 15, ty = tid >> 4;
    unsigned long long acc[4][8];
#pragma unroll
    for (int a = 0; a < 4; a++)
#pragma unroll
        for (int c = 0; c < 8; c++) acc[a][c] = 0ULL;
    int nkt = (Kdim + 15) >> 4;
    for (int kt = 0; kt < nkt; kt++) {
        int k0 = kt << 4;
        for (int i = tid; i < 2048; i += 256) {
            int j = i >> 7, mm = i & 127;
            sIn[j][mm] = (k0 + j < Kdim) ? In[(size_t)(k0 + j) * 1024 + mTile + mm] : 0.f;
        }
        for (int i = tid; i < 2048; i += 256) {
            int j = i & 15, o = i >> 4;
            sW[j][o] = (k0 + j < Kdim) ? W[(size_t)(oTile + o) * ldw + k0 + j] : 0.f;
        }
        __syncthreads();
#pragma unroll
        for (int j = 0; j < 16; j++) {
            unsigned long long iv[4], wv[8];
#pragma unroll
            for (int s = 0; s < 4; s++)
                iv[s] = *reinterpret_cast<const unsigned long long*>(&sIn[j][ty * 2 + 32 * s]);
#pragma unroll
            for (int s = 0; s < 8; s++) wv[s] = dup2(sW[j][tx + 16 * s]);
#pragma unroll
            for (int mi = 0; mi < 4; mi++)
#pragma unroll
                for (int oi = 0; oi < 8; oi++) fma2(acc[mi][oi], iv[mi], wv[oi]);
        }
        __syncthreads();
    }
#pragma unroll
    for (int mi = 0; mi < 4; mi++) {
        int m = mTile + ty * 2 + 32 * mi;
#pragma unroll
        for (int oi = 0; oi < 8; oi++) {
            int o = oTile + tx + 16 * oi;
            float lo, hi;
            asm("mov.b64 {%0, %1}, %2;" : "=f"(lo), "=f"(hi) : "l"(acc[mi][oi]));
            float add = bias ? bias[o] : 0.f;
            size_t p0 = (size_t)m * 512 + o;
            Out[p0] = lo + add;
            Out[p0 + 512] = hi + add;
        }
    }
}

// ------- stepB: gather gates, LSTM nonlin, max over k; A inline (layer0) or loaded --
__global__ __launch_bounds__(256) void stepB_kernel(
    const float* __restrict__ Abuf,           // null => inline-A from x (layer 0)
    const float* __restrict__ x, const float* __restrict__ wEA0,
    const float* __restrict__ b0,
    const float* __restrict__ Hh0, const int* __restrict__ idx_t,
    const float* __restrict__ cPrev, float* __restrict__ hOut0,
    float* __restrict__ cOut, int t) {
    __shared__ float sh[128][9];
    __shared__ float sW0[2048];
    __shared__ float sB0[512];
    int b = blockIdx.y;
    int warp = threadIdx.x >> 5, lane = threadIdx.x & 31;
    int n = blockIdx.x * 8 + warp;
    bool inlineA = (Abuf == nullptr);
    if (inlineA) {
        for (int i = threadIdx.x; i < 2048; i += 256) sW0[i] = wEA0[i];
        for (int i = threadIdx.x; i < 512; i += 256) sB0[i] = b0[i];
        __syncthreads();
    }
    float A4[4][4], hm[4], cm[4];
    if (inlineA) {
        float xv[4];
#pragma unroll
        for (int c = 0; c < 4; c++) xv[c] = x[((size_t)(b * TT + t) * 4 + c) * 1024 + n];
#pragma unroll
        for (int j = 0; j < 4; j++) {
            int d = j * 32 + lane;
#pragma unroll
            for (int g = 0; g < 4; g++) {
                int o = g * 128 + d;
                float v = sB0[o];
#pragma unroll
                for (int c = 0; c < 4; c++) v = fmaf(sW0[o * 4 + c], xv[c], v);
                A4[g][j] = v;
            }
        }
    } else {
        const float* Arow = Abuf + ((size_t)(b * TT + t) * 1024 + n) * 512;
#pragma unroll
        for (int j = 0; j < 4; j++) {
            int d = j * 32 + lane;
#pragma unroll
            for (int g = 0; g < 4; g++) A4[g][j] = Arow[g * 128 + d];
        }
    }
#pragma unroll
    for (int j = 0; j < 4; j++) { hm[j] = -3.4e38f; cm[j] = -3.4e38f; }
    const float* Hh = Hh0 + (size_t)b * 1024 * 512;
    const float* cp = cPrev + (size_t)b * 1024 * 128;
    const int* idx = idx_t + (size_t)b * (TT * 1024 * 16) + n * 16;
#pragma unroll 2
    for (int k = 0; k < 16; k++) {
        int m = idx[k];
        const float* Hr = Hh + (size_t)m * 512;
        const float* cr = cp + (size_t)m * 128;
#pragma unroll
        for (int j = 0; j < 4; j++) {
            int d = j * 32 + lane;
            float gi = A4[0][j] + Hr[d];
            float gf = A4[1][j] + Hr[128 + d];
            float go = A4[2][j] + Hr[256 + d];
            float gg = A4[3][j] + Hr[384 + d];
            float cgv = (t == 0) ? 0.f : cr[d];
            float cn = sigm(gf) * cgv + sigm(gi) * tanha(gg);
            float hn = sigm(go) * tanha(cn);
            cm[j] = fmaxf(cm[j], cn);
            hm[j] = fmaxf(hm[j], hn);
        }
    }
    float* co = cOut + ((size_t)b * 1024 + n) * 128;
#pragma unroll
    for (int j = 0; j < 4; j++) co[j * 32 + lane] = cm[j];
#pragma unroll
    for (int j = 0; j < 4; j++) sh[j * 32 + lane][warp] = hm[j];
    __syncthreads();
    float* ho = hOut0 + (size_t)b * (32L * 132 * 1024);
    int n0 = blockIdx.x * 8;
    for (int i2 = threadIdx.x; i2 < 1024; i2 += 256) {
        int d = i2 >> 3, nn = i2 & 7;
        ho[(size_t)d * 1024 + n0 + nn] = sh[d][nn];
    }
}

// ------- final: h copy from out1[t=31], c transpose [b][n][d] -> [b][d][n] --------
__global__ void final_kernel(float* __restrict__ out, const float* __restrict__ cfin) {
    int i = blockIdx.x * 256 + threadIdx.x;  // 524288 = 4*128*1024
    int b = i >> 17;
    int r = i & 131071;
    int d = r >> 10;
    int n = r & 1023;
    out[17301504 + i] = out[((size_t)((b * 32 + 31) * 132) + 4 + d) * 1024 + n];
    out[17825792 + i] = cfin[(size_t)(b * 1024 + n) * 128 + d];
}

// ---------------- launch ----------------
extern "C" void kernel_launch(void* const* d_in, const int* in_sizes, int n_in,
                              void* d_out, int out_size) {
    const float* x = (const float*)d_in[0];
    const float* w0 = (const float*)d_in[1];
    const float* b0 = (const float*)d_in[2];
    const float* w1 = (const float*)d_in[3];
    const float* b1 = (const float*)d_in[4];
    float* out = (float*)d_out;

    float *A, *out0, *Hh, *cb, *wEA0, *wEA1;
    int* idxp;
    cudaGetSymbolAddress((void**)&A, g_A);
    cudaGetSymbolAddress((void**)&out0, g_out0);
    cudaGetSymbolAddress((void**)&Hh, g_Hh);
    cudaGetSymbolAddress((void**)&cb, g_cb);
    cudaGetSymbolAddress((void**)&wEA0, g_wEA0);
    cudaGetSymbolAddress((void**)&wEA1, g_wEA1);
    cudaGetSymbolAddress((void**)&idxp, g_idx);

    const long ZH = 1024L * 512;   // Hh per-b slab / A per-z slab
    const long CS = 4L * 1024 * 128;
    const long OUTB = 32L * 132 * 1024;

    knn_kernel<<<dim3(4, 32, 4), 256>>>(x, out + 18350080, idxp);
    setup_kernel<<<264, 256>>>(w0, w1, wEA0, wEA1);
    copypos_kernel<<<2048, 256>>>(x, out, out0);

    // -------- layer 0: A inline in stepB; recurrent GEMM over out0[t-1] ch0..131 ----
    for (int t = 0; t < 32; t++) {
        int tprev = t ? t - 1 : 0;
        int Kd = t ? 132 : 4;
        gemm_kernel<<<dim3(8, 4, 4), 256>>>(out0 + (size_t)tprev * 132 * 1024, OUTB,
                                            w0 + 4, 136, Kd, nullptr, Hh, ZH);
        stepB_kernel<<<dim3(128, 4), 256>>>(nullptr, x, wEA0, b0, Hh,
                                            idxp + t * 16384, cb + (t & 1) * CS,
                                            out0 + ((size_t)t * 132 + 4) * 1024,
                                            cb + ((t + 1) & 1) * CS, t);
    }

    // -------- layer 1: hoisted A (K=132 folded over out0), recurrent over out -------
    gemm_kernel<<<dim3(8, 4, 128), 256>>>(out0, 132L * 1024, wEA1, 132, 132, b1, A, ZH);
    for (int t = 0; t < 32; t++) {
        int tprev = t ? t - 1 : 0;
        int Kd = t ? 132 : 4;
        gemm_kernel<<<dim3(8, 4, 4), 256>>>(out + (size_t)tprev * 132 * 1024, OUTB,
                                            w1 + 132, 264, Kd, nullptr, Hh, ZH);
        stepB_kernel<<<dim3(128, 4), 256>>>(A, x, nullptr, nullptr, Hh,
                                            idxp + t * 16384, cb + (t & 1) * CS,
                                            out + ((size_t)t * 132 + 4) * 1024,
                                            cb + ((t + 1) & 1) * CS, t);
    }

    final_kernel<<<2048, 256>>>(out, cb);
}

// round 10
// speedup vs baseline: 1.5469x; 1.0633x over previous
#include <cuda_runtime.h>
#include <cstdint>

#define TT 32

// ---------------- scratch (device globals: allocation-free) ----------------
static __device__ float g_A   [(size_t)128 * 1024 * 512];  // layer1 A: [b*32+t][n][512]
static __device__ float g_out0[(size_t)4 * 32 * 132 * 1024];
static __device__ float g_Hh  [(size_t)4 * 1024 * 512];
static __device__ float g_cb  [2][(size_t)4 * 1024 * 128];
static __device__ int   g_idx [(size_t)4 * 32 * 1024 * 16];
static __device__ float g_wEA0[512 * 4];
static __device__ float g_wEA1[512 * 132];

// ---------------- helpers ----------------
__device__ __forceinline__ void fma2(unsigned long long& acc, unsigned long long a,
                                     unsigned long long b) {
    asm("fma.rn.f32x2 %0, %1, %2, %3;" : "=l"(acc) : "l"(a), "l"(b), "l"(acc));
}
__device__ __forceinline__ unsigned long long dup2(float w) {
    unsigned long long r;
    asm("mov.b64 %0, {%1, %1};" : "=l"(r) : "f"(w));
    return r;
}
__device__ __forceinline__ float tanha(float x) {
    float y;
    asm("tanh.approx.f32 %0, %1;" : "=f"(y) : "f"(x));
    return y;
}
__device__ __forceinline__ float sigm(float x) {
    return fmaf(0.5f, tanha(0.5f * x), 0.5f);
}

// ---------------- KNN: stable top-16 of d2 = q2 + r2 - 2 q.r ----------------
__global__ __launch_bounds__(256) void knn_kernel(const float* __restrict__ x,
                                                  float* __restrict__ outG,
                                                  int* __restrict__ idxOut) {
    __shared__ float rx[1024], ry[1024], rz[1024], rs[1024];
    int b = blockIdx.z, t = blockIdx.y;
    int n = blockIdx.x * 256 + threadIdx.x;
    int prev = t ? t - 1 : 0;
    const float* rb = x + (size_t)(b * TT + prev) * 4 * 1024;
    for (int i = threadIdx.x; i < 1024; i += 256) {
        float a = rb[i], c = rb[1024 + i], d = rb[2048 + i];
        rx[i] = a; ry[i] = c; rz[i] = d;
        rs[i] = __fadd_rn(__fadd_rn(__fmul_rn(a, a), __fmul_rn(c, c)), __fmul_rn(d, d));
    }
    __syncthreads();
    const float* qb = x + (size_t)(b * TT + t) * 4 * 1024;
    float qx = qb[n], qy = qb[1024 + n], qz = qb[2048 + n];
    float q2 = __fadd_rn(__fadd_rn(__fmul_rn(qx, qx), __fmul_rn(qy, qy)), __fmul_rn(qz, qz));
    float bd[16]; int bi[16];
#pragma unroll
    for (int i = 0; i < 16; i++) { bd[i] = 3.4e38f; bi[i] = 0; }
    for (int m = 0; m < 1024; m++) {
        float qr = fmaf(qz, rz[m], fmaf(qy, ry[m], __fmul_rn(qx, rx[m])));
        float d2 = (q2 + rs[m]) - 2.0f * qr;
        if (d2 < bd[15]) {
            int pos = 0;
#pragma unroll
            for (int i = 0; i < 16; i++) pos += (bd[i] <= d2) ? 1 : 0;  // stable ties
#pragma unroll
            for (int i = 15; i > 0; i--)
                if (i > pos) { bd[i] = bd[i - 1]; bi[i] = bi[i - 1]; }
#pragma unroll
            for (int i = 0; i < 16; i++)
                if (i == pos) { bd[i] = d2; bi[i] = m; }
        }
    }
    size_t o = (size_t)((b * TT + t) * 1024 + n) * 16;
#pragma unroll
    for (int k = 0; k < 16; k++) { idxOut[o + k] = bi[k]; outG[o + k] = (float)bi[k]; }
}

// ------- weight prep: fold "-x_t[:4]" (pos adjust) into the A-path weights -------
__global__ void setup_kernel(const float* __restrict__ w0, const float* __restrict__ w1,
                             float* __restrict__ wEA0, float* __restrict__ wEA1) {
    int i = blockIdx.x * 256 + threadIdx.x;
    if (i < 512 * 4) {
        int o = i >> 2, j = i & 3;
        wEA0[i] = w0[o * 136 + j] - w0[o * 136 + 4 + j];
    }
    if (i < 512 * 132) {
        int o = i / 132, c = i % 132;
        float v = w1[o * 264 + c];
        if (c < 4) v -= w1[o * 264 + 132 + c];
        wEA1[i] = v;
    }
}

// ------- copy position channels into both layer-output buffers (ch 0..3 of 132) ---
__global__ void copypos_kernel(const float* __restrict__ x, float* __restrict__ out,
                               float* __restrict__ out0) {
    int i = blockIdx.x * 256 + threadIdx.x;  // 524288 = 4*32*4*1024
    int n = i & 1023;
    int c = (i >> 10) & 3;
    int bt = i >> 12;
    float v = x[i];
    size_t dst = ((size_t)bt * 132 + c) * 1024 + n;
    out[dst] = v;
    out0[dst] = v;
}

// ---- GEMM 128xBO tile: Out[z][m][o(512)] = bias[o] + sum_j W[o][j]*In_z[j][m] ----
template <int BO>
__global__ __launch_bounds__(256) void gemm_kernel(
    const float* __restrict__ In0, long inZ,
    const float* __restrict__ W, int ldw, int Kdim,
    const float* __restrict__ bias,
    float* __restrict__ Out0, long outZ) {
    __shared__ float sIn[16][128];
    __shared__ float sW[16][BO + 1];
    int z = blockIdx.z;
    const float* In = In0 + (size_t)z * inZ;
    float* Out = Out0 + (size_t)z * outZ;
    int mTile = blockIdx.x * 128;
    int oTile = blockIdx.y * BO;
    int tid = threadIdx.x;
    int tx = tid & 15, ty = tid >> 4;
    constexpr int NO = BO / 16;
    unsigned long long acc[4][NO];
#pragma unroll
    for (int a = 0; a < 4; a++)
#pragma unroll
        for (int c = 0; c < NO; c++) acc[a][c] = 0ULL;
    int nkt = (Kdim + 15) >> 4;
    for (int kt = 0; kt < nkt; kt++) {
        int k0 = kt << 4;
        for (int i = tid; i < 2048; i += 256) {
            int j = i >> 7, mm = i & 127;
            sIn[j][mm] = (k0 + j < Kdim) ? In[(size_t)(k0 + j) * 1024 + mTile + mm] : 0.f;
        }
        for (int i = tid; i < 16 * BO; i += 256) {
            int j = i & 15, o = i >> 4;
            sW[j][o] = (k0 + j < Kdim) ? W[(size_t)(oTile + o) * ldw + k0 + j] : 0.f;
        }
        __syncthreads();
#pragma unroll
        for (int j = 0; j < 16; j++) {
            unsigned long long iv[4], wv[NO];
#pragma unroll
            for (int s = 0; s < 4; s++)
                iv[s] = *reinterpret_cast<const unsigned long long*>(&sIn[j][ty * 2 + 32 * s]);
#pragma unroll
            for (int s = 0; s < NO; s++) wv[s] = dup2(sW[j][tx + 16 * s]);
#pragma unroll
            for (int mi = 0; mi < 4; mi++)
#pragma unroll
                for (int oi = 0; oi < NO; oi++) fma2(acc[mi][oi], iv[mi], wv[oi]);
        }
        __syncthreads();
    }
#pragma unroll
    for (int mi = 0; mi < 4; mi++) {
        int m = mTile + ty * 2 + 32 * mi;
#pragma unroll
        for (int oi = 0; oi < NO; oi++) {
            int o = oTile + tx + 16 * oi;
            float lo, hi;
            asm("mov.b64 {%0, %1}, %2;" : "=f"(lo), "=f"(hi) : "l"(acc[mi][oi]));
            float add = bias ? bias[o] : 0.f;
            size_t p0 = (size_t)m * 512 + o;
            Out[p0] = lo + add;
            Out[p0 + 512] = hi + add;
        }
    }
}

// ------- stepB v2: 2 warps per point, software-pipelined gather ------------------
// grid (256, 4): blockIdx.x -> 4 points, 8 warps = 4 points x 2 j-halves
__global__ __launch_bounds__(256) void stepB_kernel(
    const float* __restrict__ Abuf,           // null => inline-A from x (layer 0)
    const float* __restrict__ x, const float* __restrict__ wEA0,
    const float* __restrict__ b0,
    const float* __restrict__ Hh0, const int* __restrict__ idx_t,
    const float* __restrict__ cPrev, float* __restrict__ hOut0,
    float* __restrict__ cOut, int t) {
    __shared__ float sh[128][5];
    __shared__ float sW0[2048];
    __shared__ float sB0[512];
    int b = blockIdx.y;
    int warp = threadIdx.x >> 5, lane = threadIdx.x & 31;
    int ni = warp >> 1;          // 0..3: point within CTA
    int jj = warp & 1;           // j-half: jj=0 -> d 0..63, jj=1 -> d 64..127
    int n = blockIdx.x * 4 + ni;
    const int d0 = jj * 64 + lane;      // jl=0
    const int d1 = d0 + 32;             // jl=1
    bool inlineA = (Abuf == nullptr);
    if (inlineA) {
        for (int i = threadIdx.x; i < 2048; i += 256) sW0[i] = wEA0[i];
        for (int i = threadIdx.x; i < 512; i += 256) sB0[i] = b0[i];
        __syncthreads();
    }
    float A4[4][2], hm[2], cm[2];
    if (inlineA) {
        float xv[4];
#pragma unroll
        for (int c = 0; c < 4; c++) xv[c] = x[((size_t)(b * TT + t) * 4 + c) * 1024 + n];
#pragma unroll
        for (int jl = 0; jl < 2; jl++) {
            int d = jl ? d1 : d0;
#pragma unroll
            for (int g = 0; g < 4; g++) {
                int o = g * 128 + d;
                float v = sB0[o];
#pragma unroll
                for (int c = 0; c < 4; c++) v = fmaf(sW0[o * 4 + c], xv[c], v);
                A4[g][jl] = v;
            }
        }
    } else {
        const float* Arow = Abuf + ((size_t)(b * TT + t) * 1024 + n) * 512;
#pragma unroll
        for (int jl = 0; jl < 2; jl++) {
            int d = jl ? d1 : d0;
#pragma unroll
            for (int g = 0; g < 4; g++) A4[g][jl] = Arow[g * 128 + d];
        }
    }
#pragma unroll
    for (int jl = 0; jl < 2; jl++) { hm[jl] = -3.4e38f; cm[jl] = -3.4e38f; }

    const float* Hh = Hh0 + (size_t)b * 1024 * 512;
    const float* cp = cPrev + (size_t)b * 1024 * 128;
    const int4* idx4 = reinterpret_cast<const int4*>(
        idx_t + (size_t)b * (TT * 1024 * 16) + n * 16);
    int im[16];
#pragma unroll
    for (int q = 0; q < 4; q++) {
        int4 v = idx4[q];
        im[q * 4] = v.x; im[q * 4 + 1] = v.y; im[q * 4 + 2] = v.z; im[q * 4 + 3] = v.w;
    }
    // double-buffered gather: ph[buf][jl*4+g], pc[buf][jl]
    float ph[2][8], pc[2][2];
    {
        const float* Hr = Hh + (size_t)im[0] * 512;
#pragma unroll
        for (int g = 0; g < 4; g++) {
            ph[0][g] = Hr[g * 128 + d0];
            ph[0][4 + g] = Hr[g * 128 + d1];
        }
        if (t) {
            const float* cr = cp + (size_t)im[0] * 128;
            pc[0][0] = cr[d0]; pc[0][1] = cr[d1];
        }
    }
#pragma unroll
    for (int k = 0; k < 16; k++) {
        int cur = k & 1, nxt = cur ^ 1;
        if (k < 15) {
            const float* Hr = Hh + (size_t)im[k + 1] * 512;
#pragma unroll
            for (int g = 0; g < 4; g++) {
                ph[nxt][g] = Hr[g * 128 + d0];
                ph[nxt][4 + g] = Hr[g * 128 + d1];
            }
            if (t) {
                const float* cr = cp + (size_t)im[k + 1] * 128;
                pc[nxt][0] = cr[d0]; pc[nxt][1] = cr[d1];
            }
        }
#pragma unroll
        for (int jl = 0; jl < 2; jl++) {
            float gi = A4[0][jl] + ph[cur][jl * 4 + 0];
            float gf = A4[1][jl] + ph[cur][jl * 4 + 1];
            float go = A4[2][jl] + ph[cur][jl * 4 + 2];
            float gg = A4[3][jl] + ph[cur][jl * 4 + 3];
            float cgv = t ? pc[cur][jl] : 0.f;
            float cn = sigm(gf) * cgv + sigm(gi) * tanha(gg);
            float hn = sigm(go) * tanha(cn);
            cm[jl] = fmaxf(cm[jl], cn);
            hm[jl] = fmaxf(hm[jl], hn);
        }
    }
    float* co = cOut + ((size_t)b * 1024 + n) * 128;
    co[d0] = cm[0];
    co[d1] = cm[1];
    sh[d0][ni] = hm[0];
    sh[d1][ni] = hm[1];
    __syncthreads();
    float* ho = hOut0 + (size_t)b * (32L * 132 * 1024);
    int n0 = blockIdx.x * 4;
    for (int i2 = threadIdx.x; i2 < 512; i2 += 256) {
        int d = i2 >> 2, nn = i2 & 3;
        ho[(size_t)d * 1024 + n0 + nn] = sh[d][nn];
    }
}

// ------- final: h copy from out1[t=31], c transpose [b][n][d] -> [b][d][n] --------
__global__ void final_kernel(float* __restrict__ out, const float* __restrict__ cfin) {
    int i = blockIdx.x * 256 + threadIdx.x;  // 524288 = 4*128*1024
    int b = i >> 17;
    int r = i & 131071;
    int d = r >> 10;
    int n = r & 1023;
    out[17301504 + i] = out[((size_t)((b * 32 + 31) * 132) + 4 + d) * 1024 + n];
    out[17825792 + i] = cfin[(size_t)(b * 1024 + n) * 128 + d];
}

// ---------------- launch ----------------
extern "C" void kernel_launch(void* const* d_in, const int* in_sizes, int n_in,
                              void* d_out, int out_size) {
    const float* x = (const float*)d_in[0];
    const float* w0 = (const float*)d_in[1];
    const float* b0 = (const float*)d_in[2];
    const float* w1 = (const float*)d_in[3];
    const float* b1 = (const float*)d_in[4];
    float* out = (float*)d_out;

    float *A, *out0, *Hh, *cb, *wEA0, *wEA1;
    int* idxp;
    cudaGetSymbolAddress((void**)&A, g_A);
    cudaGetSymbolAddress((void**)&out0, g_out0);
    cudaGetSymbolAddress((void**)&Hh, g_Hh);
    cudaGetSymbolAddress((void**)&cb, g_cb);
    cudaGetSymbolAddress((void**)&wEA0, g_wEA0);
    cudaGetSymbolAddress((void**)&wEA1, g_wEA1);
    cudaGetSymbolAddress((void**)&idxp, g_idx);

    const long ZH = 1024L * 512;
    const long CS = 4L * 1024 * 128;
    const long OUTB = 32L * 132 * 1024;

    knn_kernel<<<dim3(4, 32, 4), 256>>>(x, out + 18350080, idxp);
    setup_kernel<<<264, 256>>>(w0, w1, wEA0, wEA1);
    copypos_kernel<<<2048, 256>>>(x, out, out0);

    // -------- layer 0: A inline in stepB; recurrent GEMM over out0[t-1] ch0..131 ----
    for (int t = 0; t < 32; t++) {
        int tprev = t ? t - 1 : 0;
        int Kd = t ? 132 : 4;
        gemm_kernel<64><<<dim3(8, 8, 4), 256>>>(out0 + (size_t)tprev * 132 * 1024, OUTB,
                                                w0 + 4, 136, Kd, nullptr, Hh, ZH);
        stepB_kernel<<<dim3(256, 4), 256>>>(nullptr, x, wEA0, b0, Hh,
                                            idxp + t * 16384, cb + (t & 1) * CS,
                                            out0 + ((size_t)t * 132 + 4) * 1024,
                                            cb + ((t + 1) & 1) * CS, t);
    }

    // -------- layer 1: hoisted A (K=132 folded over out0), recurrent over out -------
    gemm_kernel<128><<<dim3(8, 4, 128), 256>>>(out0, 132L * 1024, wEA1, 132, 132, b1,
                                               A, ZH);
    for (int t = 0; t < 32; t++) {
        int tprev = t ? t - 1 : 0;
        int Kd = t ? 132 : 4;
        gemm_kernel<64><<<dim3(8, 8, 4), 256>>>(out + (size_t)tprev * 132 * 1024, OUTB,
                                                w1 + 132, 264, Kd, nullptr, Hh, ZH);
        stepB_kernel<<<dim3(256, 4), 256>>>(A, x, nullptr, nullptr, Hh,
                                            idxp + t * 16384, cb + (t & 1) * CS,
                                            out + ((size_t)t * 132 + 4) * 1024,
                                            cb + ((t + 1) & 1) * CS, t);
    }

    final_kernel<<<2048, 256>>>(out, cb);
}

// round 13
// speedup vs baseline: 1.5871x; 1.0260x over previous
#include <cuda_runtime.h>
#include <cuda_fp16.h>
#include <cstdint>

#define TT 32

// ---------------- scratch (device globals: allocation-free) ----------------
static __device__ __half g_A [(size_t)128 * 1024 * 512];  // layer1 A (fp16)
static __device__ float g_out0[(size_t)4 * 32 * 132 * 1024];
static __device__ __half g_Hh[(size_t)4 * 1024 * 512];    // gates from GEMM (fp16)
static __device__ float g_cb  [2][(size_t)4 * 1024 * 128];
static __device__ int   g_idx [(size_t)4 * 32 * 1024 * 16];
static __device__ float g_wEA0[512 * 4];
static __device__ float g_wEA1[512 * 132];

// ---------------- helpers ----------------
__device__ __forceinline__ void fma2(unsigned long long& acc, unsigned long long a,
                                     unsigned long long b) {
    asm("fma.rn.f32x2 %0, %1, %2, %3;" : "=l"(acc) : "l"(a), "l"(b), "l"(acc));
}
__device__ __forceinline__ unsigned long long dup2(float w) {
    unsigned long long r;
    asm("mov.b64 %0, {%1, %1};" : "=l"(r) : "f"(w));
    return r;
}
__device__ __forceinline__ float tanha(float x) {
    float y;
    asm("tanh.approx.f32 %0, %1;" : "=f"(y) : "f"(x));
    return y;
}
__device__ __forceinline__ float sigm(float x) {
    return fmaf(0.5f, tanha(0.5f * x), 0.5f);
}

// ---------------- KNN: stable top-16 of d2 = q2 + r2 - 2 q.r ----------------
__global__ __launch_bounds__(256) void knn_kernel(const float* __restrict__ x,
                                                  float* __restrict__ outG,
                                                  int* __restrict__ idxOut) {
    __shared__ float rx[1024], ry[1024], rz[1024], rs[1024];
    int b = blockIdx.z, t = blockIdx.y;
    int n = blockIdx.x * 256 + threadIdx.x;
    int prev = t ? t - 1 : 0;
    const float* rb = x + (size_t)(b * TT + prev) * 4 * 1024;
    for (int i = threadIdx.x; i < 1024; i += 256) {
        float a = rb[i], c = rb[1024 + i], d = rb[2048 + i];
        rx[i] = a; ry[i] = c; rz[i] = d;
        rs[i] = __fadd_rn(__fadd_rn(__fmul_rn(a, a), __fmul_rn(c, c)), __fmul_rn(d, d));
    }
    __syncthreads();
    const float* qb = x + (size_t)(b * TT + t) * 4 * 1024;
    float qx = qb[n], qy = qb[1024 + n], qz = qb[2048 + n];
    float q2 = __fadd_rn(__fadd_rn(__fmul_rn(qx, qx), __fmul_rn(qy, qy)), __fmul_rn(qz, qz));
    float bd[16]; int bi[16];
#pragma unroll
    for (int i = 0; i < 16; i++) { bd[i] = 3.4e38f; bi[i] = 0; }
    for (int m = 0; m < 1024; m++) {
        float qr = fmaf(qz, rz[m], fmaf(qy, ry[m], __fmul_rn(qx, rx[m])));
        float d2 = (q2 + rs[m]) - 2.0f * qr;
        if (d2 < bd[15]) {
            int pos = 0;
#pragma unroll
            for (int i = 0; i < 16; i++) pos += (bd[i] <= d2) ? 1 : 0;  // stable ties
#pragma unroll
            for (int i = 15; i > 0; i--)
                if (i > pos) { bd[i] = bd[i - 1]; bi[i] = bi[i - 1]; }
#pragma unroll
            for (int i = 0; i < 16; i++)
                if (i == pos) { bd[i] = d2; bi[i] = m; }
        }
    }
    size_t o = (size_t)((b * TT + t) * 1024 + n) * 16;
#pragma unroll
    for (int k = 0; k < 16; k++) { idxOut[o + k] = bi[k]; outG[o + k] = (float)bi[k]; }
}

// ---- prep: fold pos-adjust into A-path weights + copy position channels ----
__global__ void prep_kernel(const float* __restrict__ x,
                            const float* __restrict__ w0, const float* __restrict__ w1,
                            float* __restrict__ out, float* __restrict__ out0,
                            float* __restrict__ wEA0, float* __restrict__ wEA1) {
    int i = blockIdx.x * 256 + threadIdx.x;  // 524288 threads
    if (i < 512 * 4) {
        int o = i >> 2, j = i & 3;
        wEA0[i] = w0[o * 136 + j] - w0[o * 136 + 4 + j];
    }
    if (i < 512 * 132) {
        int o = i / 132, c = i % 132;
        float v = w1[o * 264 + c];
        if (c < 4) v -= w1[o * 264 + 132 + c];
        wEA1[i] = v;
    }
    // copypos: 524288 = 4*32*4*1024
    int n = i & 1023;
    int c = (i >> 10) & 3;
    int bt = i >> 12;
    float v = x[i];
    size_t dst = ((size_t)bt * 132 + c) * 1024 + n;
    out[dst] = v;
    out0[dst] = v;
}

// ---- GEMM 128xBO tile -> fp16: Out[z][m][o] = bias[o] + sum_j W[o][j]*In_z[j][m] ----
template <int BO>
__global__ __launch_bounds__(256) void gemm_kernel(
    const float* __restrict__ In0, long inZ,
    const float* __restrict__ W, int ldw, int Kdim,
    const float* __restrict__ bias,
    __half* __restrict__ Out0, long outZ) {
    __shared__ float sIn[16][128];
    __shared__ float sW[16][BO + 1];
    int z = blockIdx.z;
    const float* In = In0 + (size_t)z * inZ;
    __half* Out = Out0 + (size_t)z * outZ;
    int mTile = blockIdx.x * 128;
    int oTile = blockIdx.y * BO;
    int tid = threadIdx.x;
    int tx = tid & 15, ty = tid >> 4;
    constexpr int NO = BO / 16;
    unsigned long long acc[4][NO];
#pragma unroll
    for (int a = 0; a < 4; a++)
#pragma unroll
        for (int c = 0; c < NO; c++) acc[a][c] = 0ULL;
    int nkt = (Kdim + 15) >> 4;
    for (int kt = 0; kt < nkt; kt++) {
        int k0 = kt << 4;
        for (int i = tid; i < 2048; i += 256) {
            int j = i >> 7, mm = i & 127;
            sIn[j][mm] = (k0 + j < Kdim) ? In[(size_t)(k0 + j) * 1024 + mTile + mm] : 0.f;
        }
        for (int i = tid; i < 16 * BO; i += 256) {
            int j = i & 15, o = i >> 4;
            sW[j][o] = (k0 + j < Kdim) ? W[(size_t)(oTile + o) * ldw + k0 + j] : 0.f;
        }
        __syncthreads();
#pragma unroll
        for (int j = 0; j < 16; j++) {
            unsigned long long iv[4], wv[NO];
#pragma unroll
            for (int s = 0; s < 4; s++)
                iv[s] = *reinterpret_cast<const unsigned long long*>(&sIn[j][ty * 2 + 32 * s]);
#pragma unroll
            for (int s = 0; s < NO; s++) wv[s] = dup2(sW[j][tx + 16 * s]);
#pragma unroll
            for (int mi = 0; mi < 4; mi++)
#pragma unroll
                for (int oi = 0; oi < NO; oi++) fma2(acc[mi][oi], iv[mi], wv[oi]);
        }
        __syncthreads();
    }
#pragma unroll
    for (int mi = 0; mi < 4; mi++) {
        int m = mTile + ty * 2 + 32 * mi;
#pragma unroll
        for (int oi = 0; oi < NO; oi++) {
            int o = oTile + tx + 16 * oi;
            float lo, hi;
            asm("mov.b64 {%0, %1}, %2;" : "=f"(lo), "=f"(hi) : "l"(acc[mi][oi]));
            float add = bias ? bias[o] : 0.f;
            size_t p0 = (size_t)m * 512 + o;
            Out[p0] = __float2half_rn(lo + add);
            Out[p0 + 512] = __float2half_rn(hi + add);
        }
    }
}

// ------- stepB v4: fp16 gather, d-pair threads, 4-deep chunked prefetch ----------
// grid (256, 4): 8 warps = 4 points x 2 d-halves; thread -> (d, d+1)
__global__ __launch_bounds__(256) void stepB_kernel(
    const __half* __restrict__ Abuf,          // null => inline-A from x (layer 0)
    const float* __restrict__ x, const float* __restrict__ wEA0,
    const float* __restrict__ b0,
    const __half* __restrict__ Hh0, const int* __restrict__ idx_t,
    const float* __restrict__ cPrev, float* __restrict__ hOut0,
    float* __restrict__ cOut, int t) {
    __shared__ float sh[128][5];
    __shared__ float sW0[2048];
    __shared__ float sB0[512];
    int b = blockIdx.y;
    int tid = threadIdx.x;
    int warp = tid >> 5, lane = tid & 31;
    int ni = warp >> 1;          // point within CTA
    int jj = warp & 1;           // d-half
    int n = blockIdx.x * 4 + ni;
    const int d = jj * 64 + lane * 2;   // this thread: d, d+1
    bool inlineA = (Abuf == nullptr);
    if (inlineA) {
        for (int i = tid; i < 2048; i += 256) sW0[i] = wEA0[i];
        for (int i = tid; i < 512; i += 256) sB0[i] = b0[i];
        __syncthreads();
    }
    float A4[4][2], hm[2], cm[2];
    if (inlineA) {
        float xv[4];
#pragma unroll
        for (int c = 0; c < 4; c++) xv[c] = x[((size_t)(b * TT + t) * 4 + c) * 1024 + n];
#pragma unroll
        for (int g = 0; g < 4; g++)
#pragma unroll
            for (int hf = 0; hf < 2; hf++) {
                int o = g * 128 + d + hf;
                float v = sB0[o];
#pragma unroll
                for (int c = 0; c < 4; c++) v = fmaf(sW0[o * 4 + c], xv[c], v);
                A4[g][hf] = v;
            }
    } else {
        const __half2* Ar = reinterpret_cast<const __half2*>(
            Abuf + ((size_t)(b * TT + t) * 1024 + n) * 512);
#pragma unroll
        for (int g = 0; g < 4; g++) {
            float2 v = __half22float2(Ar[(g * 128 + d) >> 1]);
            A4[g][0] = v.x;
            A4[g][1] = v.y;
        }
    }
    hm[0] = hm[1] = -3.4e38f;
    cm[0] = cm[1] = -3.4e38f;

    const __half2* Hh2 =
        reinterpret_cast<const __half2*>(Hh0) + (size_t)b * 1024 * 256;
    const float* cp = cPrev + (size_t)b * 1024 * 128;
    const int4* idx4 = reinterpret_cast<const int4*>(
        idx_t + (size_t)b * (TT * 1024 * 16) + n * 16);
    int im[16];
#pragma unroll
    for (int q = 0; q < 4; q++) {
        int4 v = idx4[q];
        im[q * 4] = v.x; im[q * 4 + 1] = v.y; im[q * 4 + 2] = v.z; im[q * 4 + 3] = v.w;
    }
    // 4-deep chunked double buffer: bh[buf][k-in-chunk][gate], cc[buf][k-in-chunk]
    __half2 bh[2][4][4];
    float2 cc[2][4];
#pragma unroll
    for (int kk = 0; kk < 4; kk++) {
        int base = im[kk] * 256 + jj * 32 + lane;
#pragma unroll
        for (int g = 0; g < 4; g++) bh[0][kk][g] = Hh2[base + g * 64];
        cc[0][kk] = t ? *reinterpret_cast<const float2*>(cp + (size_t)im[kk] * 128 + d)
                      : make_float2(0.f, 0.f);
    }
#pragma unroll
    for (int ch = 0; ch < 4; ch++) {
        int cur = ch & 1, nxt = cur ^ 1;
        if (ch < 3) {
#pragma unroll
            for (int kk = 0; kk < 4; kk++) {
                int k = (ch + 1) * 4 + kk;
                int base = im[k] * 256 + jj * 32 + lane;
#pragma unroll
                for (int g = 0; g < 4; g++) bh[nxt][kk][g] = Hh2[base + g * 64];
                cc[nxt][kk] = t ? *reinterpret_cast<const float2*>(
                                      cp + (size_t)im[k] * 128 + d)
                                : make_float2(0.f, 0.f);
            }
        }
#pragma unroll
        for (int kk = 0; kk < 4; kk++) {
            float2 hv[4];
#pragma unroll
            for (int g = 0; g < 4; g++) hv[g] = __half22float2(bh[cur][kk][g]);
            float2 cgv = cc[cur][kk];
            {
                float gi = A4[0][0] + hv[0].x, gf = A4[1][0] + hv[1].x;
                float go = A4[2][0] + hv[2].x, gg = A4[3][0] + hv[3].x;
                float cn = sigm(gf) * cgv.x + sigm(gi) * tanha(gg);
                float hn = sigm(go) * tanha(cn);
                cm[0] = fmaxf(cm[0], cn);
                hm[0] = fmaxf(hm[0], hn);
            }
            {
                float gi = A4[0][1] + hv[0].y, gf = A4[1][1] + hv[1].y;
                float go = A4[2][1] + hv[2].y, gg = A4[3][1] + hv[3].y;
                float cn = sigm(gf) * cgv.y + sigm(gi) * tanha(gg);
                float hn = sigm(go) * tanha(cn);
                cm[1] = fmaxf(cm[1], cn);
                hm[1] = fmaxf(hm[1], hn);
            }
        }
    }
    *reinterpret_cast<float2*>(cOut + ((size_t)b * 1024 + n) * 128 + d) =
        make_float2(cm[0], cm[1]);
    sh[d][ni] = hm[0];
    sh[d + 1][ni] = hm[1];
    __syncthreads();
    float* ho = hOut0 + (size_t)b * (32L * 132 * 1024);
    int n0 = blockIdx.x * 4;
    for (int i2 = tid; i2 < 512; i2 += 256) {
        int dd = i2 >> 2, nn = i2 & 3;
        ho[(size_t)dd * 1024 + n0 + nn] = sh[dd][nn];
    }
}

// ------- final: h copy from out1[t=31], c transpose [b][n][d] -> [b][d][n] --------
__global__ void final_kernel(float* __restrict__ out, const float* __restrict__ cfin) {
    int i = blockIdx.x * 256 + threadIdx.x;  // 524288 = 4*128*1024
    int b = i >> 17;
    int r = i & 131071;
    int d = r >> 10;
    int n = r & 1023;
    out[17301504 + i] = out[((size_t)((b * 32 + 31) * 132) + 4 + d) * 1024 + n];
    out[17825792 + i] = cfin[(size_t)(b * 1024 + n) * 128 + d];
}

// ---------------- launch ----------------
extern "C" void kernel_launch(void* const* d_in, const int* in_sizes, int n_in,
                              void* d_out, int out_size) {
    const float* x = (const float*)d_in[0];
    const float* w0 = (const float*)d_in[1];
    const float* b0 = (const float*)d_in[2];
    const float* w1 = (const float*)d_in[3];
    const float* b1 = (const float*)d_in[4];
    float* out = (float*)d_out;

    __half *A, *Hh;
    float *out0, *cb, *wEA0, *wEA1;
    int* idxp;
    cudaGetSymbolAddress((void**)&A, g_A);
    cudaGetSymbolAddress((void**)&out0, g_out0);
    cudaGetSymbolAddress((void**)&Hh, g_Hh);
    cudaGetSymbolAddress((void**)&cb, g_cb);
    cudaGetSymbolAddress((void**)&wEA0, g_wEA0);
    cudaGetSymbolAddress((void**)&wEA1, g_wEA1);
    cudaGetSymbolAddress((void**)&idxp, g_idx);

    const long ZH = 1024L * 512;   // fp16 elements per z-slab
    const long CS = 4L * 1024 * 128;
    const long OUTB = 32L * 132 * 1024;

    knn_kernel<<<dim3(4, 32, 4), 256>>>(x, out + 18350080, idxp);
    prep_kernel<<<2048, 256>>>(x, w0, w1, out, out0, wEA0, wEA1);

    // -------- layer 0: A inline in stepB; recurrent GEMM over out0[t-1] ch0..131 ----
    // (launch #6 under ncu -s 5 -c 1 = stepB t=1 -> stepB finally gets profiled)
    for (int t = 0; t < 32; t++) {
        int tprev = t ? t - 1 : 0;
        int Kd = t ? 132 : 4;
        gemm_kernel<64><<<dim3(8, 8, 4), 256>>>(out0 + (size_t)tprev * 132 * 1024, OUTB,
                                                w0 + 4, 136, Kd, nullptr, Hh, ZH);
        stepB_kernel<<<dim3(256, 4), 256>>>(nullptr, x, wEA0, b0, Hh,
                                            idxp + t * 16384, cb + (t & 1) * CS,
                                            out0 + ((size_t)t * 132 + 4) * 1024,
                                            cb + ((t + 1) & 1) * CS, t);
    }

    // -------- layer 1: hoisted A (K=132 folded over out0), recurrent over out -------
    gemm_kernel<128><<<dim3(8, 4, 128), 256>>>(out0, 132L * 1024, wEA1, 132, 132, b1,
                                               A, ZH);
    for (int t = 0; t < 32; t++) {
        int tprev = t ? t - 1 : 0;
        int Kd = t ? 132 : 4;
        gemm_kernel<64><<<dim3(8, 8, 4), 256>>>(out + (size_t)tprev * 132 * 1024, OUTB,
                                                w1 + 132, 264, Kd, nullptr, Hh, ZH);
        stepB_kernel<<<dim3(256, 4), 256>>>(A, x, nullptr, nullptr, Hh,
                                            idxp + t * 16384, cb + (t & 1) * CS,
                                            out + ((size_t)t * 132 + 4) * 1024,
                                            cb + ((t + 1) & 1) * CS, t);
    }

    final_kernel<<<2048, 256>>>(out, cb);
}